// round 1
// baseline (speedup 1.0000x reference)
#include <cuda_runtime.h>
#include <math.h>

// ---------------- problem constants ----------------
#define Cc   128      // channels (d_model)
#define Hd   128
#define Wd   128
#define HWs  16384    // H*W
#define BT   16       // b*t images
#define NB   2        // batch b
#define TT   8        // frames per clip

// ---------------- device scratch (no cudaMalloc allowed) ----------------
__device__ float g_q [(size_t)BT * Cc * HWs];
__device__ float g_k [(size_t)BT * Cc * HWs];
__device__ float g_v [(size_t)BT * Cc * HWs];
__device__ float g_ao[(size_t)BT * Cc * HWs];
__device__ float g_part[(size_t)1 << 22];     // partial scores (max 4M floats)
__device__ float g_attn[(size_t)NB * 512 * 512];

// ---------------- window gather addressing ----------------
// token = ((t*oh + oy)*ow + ox), feature e = ((c*ph + py)*pw + px), square windows.
__device__ __forceinline__ size_t win_addr(int b, int cslice, int token, int e,
                                           int lph, int loh)
{
    int pm = (1 << lph) - 1;
    int om = (1 << loh) - 1;
    int px = e & pm;
    int py = (e >> lph) & pm;
    int c  = e >> (2 * lph);
    int ox = token & om;
    int oy = (token >> loh) & om;
    int t  = token >> (2 * loh);
    int img = b * TT + t;
    int yy = (oy << lph) + py;
    int xx = (ox << lph) + px;
    return ((size_t)(img * Cc + cslice + c)) * HWs + (size_t)yy * Wd + xx;
}

// ---------------- kernel 1: fused conv1x1 (one of q/k/v per launch) ----------------
__global__ __launch_bounds__(256)
void conv1x1_kernel(const float* __restrict__ x,
                    const float* __restrict__ w,
                    const float* __restrict__ bias,
                    int which)
{
    __shared__ float Xs[16][128];
    __shared__ float Ws[16][128];
    float* out = (which == 0) ? g_q : (which == 1) ? g_k : g_v;

    int n  = blockIdx.y;
    int p0 = blockIdx.x * 128;
    int tx = threadIdx.x, ty = threadIdx.y;
    int tid = ty * 16 + tx;

    float acc[8][8];
#pragma unroll
    for (int i = 0; i < 8; i++)
#pragma unroll
        for (int j = 0; j < 8; j++) acc[i][j] = 0.f;

    const float* xb = x + (size_t)n * Cc * HWs;

    for (int k0 = 0; k0 < Cc; k0 += 16) {
        {
            int kk = tid >> 7;        // 0..1
            int pp = tid & 127;
#pragma unroll
            for (int r = 0; r < 8; r++)
                Xs[kk + 2 * r][pp] = xb[(size_t)(k0 + kk + 2 * r) * HWs + p0 + pp];
        }
        {
            int kk = tid & 15;
            int oc = tid >> 4;        // 0..15
#pragma unroll
            for (int r = 0; r < 8; r++)
                Ws[kk][oc + 16 * r] = w[(size_t)(oc + 16 * r) * Cc + k0 + kk];
        }
        __syncthreads();
#pragma unroll
        for (int kk = 0; kk < 16; kk++) {
            float xr[8], wr[8];
#pragma unroll
            for (int j = 0; j < 8; j++) xr[j] = Xs[kk][tx + 16 * j];
#pragma unroll
            for (int i = 0; i < 8; i++) wr[i] = Ws[kk][ty + 16 * i];
#pragma unroll
            for (int i = 0; i < 8; i++)
#pragma unroll
                for (int j = 0; j < 8; j++) acc[i][j] += wr[i] * xr[j];
        }
        __syncthreads();
    }

#pragma unroll
    for (int i = 0; i < 8; i++) {
        int oc = ty + 16 * i;
        float bv = bias[oc];
#pragma unroll
        for (int j = 0; j < 8; j++)
            out[((size_t)n * Cc + oc) * HWs + p0 + tx + 16 * j] = acc[i][j] + bv;
    }
}

// ---------------- kernel 2: windowed scores (partial over d-splits) ----------------
template<int BN, int BM, int TN, int TM>
__global__ __launch_bounds__(256)
void scores_kernel(int n, int cslice, int lph, int loh,
                   int tilesM, int dchunk)
{
    __shared__ float Qs[BN][33];
    __shared__ float Ks[BM][33];

    int b  = blockIdx.y;
    int z  = blockIdx.z;
    int tn = blockIdx.x / tilesM;
    int tm = blockIdx.x - tn * tilesM;
    int n0 = tn * BN, m0 = tm * BM;
    int tx = threadIdx.x, ty = threadIdx.y;
    int tid = ty * 16 + tx;

    float acc[TN][TM];
#pragma unroll
    for (int i = 0; i < TN; i++)
#pragma unroll
        for (int j = 0; j < TM; j++) acc[i][j] = 0.f;

    int r0 = ty * TN, c0 = tx * TM;
    bool active = (r0 < BN) && (c0 < BM);

    int kstart = z * dchunk;
    int kend   = kstart + dchunk;

    for (int k0 = kstart; k0 < kend; k0 += 32) {
        for (int idx = tid; idx < BN * 32; idx += 256) {
            int r = idx >> 5, cc = idx & 31;
            Qs[r][cc] = g_q[win_addr(b, cslice, n0 + r, k0 + cc, lph, loh)];
        }
        for (int idx = tid; idx < BM * 32; idx += 256) {
            int r = idx >> 5, cc = idx & 31;
            Ks[r][cc] = g_k[win_addr(b, cslice, m0 + r, k0 + cc, lph, loh)];
        }
        __syncthreads();
        if (active) {
#pragma unroll
            for (int kk = 0; kk < 32; kk++) {
                float qr[TN], kr[TM];
#pragma unroll
                for (int i = 0; i < TN; i++) qr[i] = Qs[r0 + i][kk];
#pragma unroll
                for (int j = 0; j < TM; j++) kr[j] = Ks[c0 + j][kk];
#pragma unroll
                for (int i = 0; i < TN; i++)
#pragma unroll
                    for (int j = 0; j < TM; j++) acc[i][j] += qr[i] * kr[j];
            }
        }
        __syncthreads();
    }

    if (active) {
        size_t base = ((size_t)(z * NB + b)) * n * n;
#pragma unroll
        for (int i = 0; i < TN; i++)
#pragma unroll
            for (int j = 0; j < TM; j++)
                g_part[base + (size_t)(n0 + r0 + i) * n + (m0 + c0 + j)] = acc[i][j];
    }
}

// ---------------- kernel 3: reduce partials + softmax ----------------
__global__ __launch_bounds__(256)
void softmax_kernel(int n, int nsplit, float inv_sqrt_d)
{
    __shared__ float sbuf[512];
    __shared__ float red[256];
    int row = blockIdx.x;
    int b   = blockIdx.y;
    int tid = threadIdx.x;

    for (int m = tid; m < n; m += 256) {
        float s = 0.f;
        for (int z = 0; z < nsplit; z++)
            s += g_part[((size_t)(z * NB + b) * n + row) * n + m];
        sbuf[m] = s * inv_sqrt_d;
    }
    __syncthreads();

    float lm = -1e30f;
    for (int m = tid; m < n; m += 256) lm = fmaxf(lm, sbuf[m]);
    red[tid] = lm;
    __syncthreads();
    for (int s = 128; s > 0; s >>= 1) {
        if (tid < s) red[tid] = fmaxf(red[tid], red[tid + s]);
        __syncthreads();
    }
    float mx = red[0];
    __syncthreads();

    float ls = 0.f;
    for (int m = tid; m < n; m += 256) {
        float e = expf(sbuf[m] - mx);
        sbuf[m] = e;
        ls += e;
    }
    red[tid] = ls;
    __syncthreads();
    for (int s = 128; s > 0; s >>= 1) {
        if (tid < s) red[tid] += red[tid + s];
        __syncthreads();
    }
    float inv = 1.0f / red[0];

    for (int m = tid; m < n; m += 256)
        g_attn[((size_t)b * n + row) * n + m] = sbuf[m] * inv;
}

// ---------------- kernel 4: AV (attn @ V, scattered back to image layout) ----------------
template<int BN, int TN>
__global__ __launch_bounds__(256)
void av_kernel(int n, int cslice, int lph, int loh)
{
    __shared__ float As[BN][33];
    __shared__ float Vs[32][64];

    int b  = blockIdx.z;
    int n0 = blockIdx.y * BN;
    int e0 = blockIdx.x * 64;
    int tx = threadIdx.x, ty = threadIdx.y;
    int tid = ty * 16 + tx;

    float acc[TN][4];
#pragma unroll
    for (int i = 0; i < TN; i++)
#pragma unroll
        for (int j = 0; j < 4; j++) acc[i][j] = 0.f;

    int r0 = ty * TN;
    bool active = (r0 < BN);

    for (int m0 = 0; m0 < n; m0 += 32) {
        for (int idx = tid; idx < BN * 32; idx += 256) {
            int r = idx >> 5, cc = idx & 31;
            As[r][cc] = (m0 + cc < n)
                ? g_attn[((size_t)b * n + n0 + r) * n + m0 + cc] : 0.f;
        }
        for (int idx = tid; idx < 32 * 64; idx += 256) {
            int mm = idx >> 6, ee = idx & 63;
            Vs[mm][ee] = (m0 + mm < n)
                ? g_v[win_addr(b, cslice, m0 + mm, e0 + ee, lph, loh)] : 0.f;
        }
        __syncthreads();
        if (active) {
#pragma unroll
            for (int kk = 0; kk < 32; kk++) {
                float vr[4];
#pragma unroll
                for (int j = 0; j < 4; j++) vr[j] = Vs[kk][tx * 4 + j];
#pragma unroll
                for (int i = 0; i < TN; i++) {
                    float a = As[r0 + i][kk];
#pragma unroll
                    for (int j = 0; j < 4; j++) acc[i][j] += a * vr[j];
                }
            }
        }
        __syncthreads();
    }

    if (active) {
#pragma unroll
        for (int i = 0; i < TN; i++)
#pragma unroll
            for (int j = 0; j < 4; j++)
                g_ao[win_addr(b, cslice, n0 + r0 + i, e0 + tx * 4 + j, lph, loh)] = acc[i][j];
    }
}

// ---------------- kernel 5: conv3x3 SAME + bias + relu ----------------
__global__ __launch_bounds__(256)
void conv3x3_kernel(const float* __restrict__ w,
                    const float* __restrict__ bias,
                    float* __restrict__ out)
{
    __shared__ float xr[3][130];
    __shared__ float ws[9][128];

    int n = blockIdx.y;
    int y = blockIdx.x;
    int tx = threadIdx.x, ty = threadIdx.y;
    int tid = ty * 16 + tx;

    float acc[8][8];
#pragma unroll
    for (int i = 0; i < 8; i++)
#pragma unroll
        for (int j = 0; j < 8; j++) acc[i][j] = 0.f;

    const float* in = g_ao + (size_t)n * Cc * HWs;

    for (int c = 0; c < Cc; c++) {
        for (int i = tid; i < 3 * 130; i += 256) {
            int ry = i / 130, rx = i - ry * 130;
            int yy = y + ry - 1, xx = rx - 1;
            float v = 0.f;
            if (yy >= 0 && yy < Hd && xx >= 0 && xx < Wd)
                v = in[(size_t)c * HWs + (size_t)yy * Wd + xx];
            xr[ry][rx] = v;
        }
        for (int i = tid; i < 1152; i += 256) {
            int oc = i / 9, tap = i - oc * 9;
            ws[tap][oc] = w[((size_t)oc * Cc + c) * 9 + tap];
        }
        __syncthreads();

#pragma unroll
        for (int ky = 0; ky < 3; ky++) {
#pragma unroll
            for (int kx = 0; kx < 3; kx++) {
                float wr[8];
#pragma unroll
                for (int i = 0; i < 8; i++) wr[i] = ws[ky * 3 + kx][ty + 16 * i];
#pragma unroll
                for (int j = 0; j < 8; j++) {
                    float xv = xr[ky][tx + 16 * j + kx];
#pragma unroll
                    for (int i = 0; i < 8; i++) acc[i][j] += wr[i] * xv;
                }
            }
        }
        __syncthreads();
    }

#pragma unroll
    for (int i = 0; i < 8; i++) {
        int oc = ty + 16 * i;
        float bv = bias[oc];
#pragma unroll
        for (int j = 0; j < 8; j++) {
            float v = acc[i][j] + bv;
            out[((size_t)(n * Cc + oc)) * HWs + (size_t)y * Wd + tx + 16 * j] =
                fmaxf(v, 0.f);
        }
    }
}

// ---------------- launch ----------------
extern "C" void kernel_launch(void* const* d_in, const int* in_sizes, int n_in,
                              void* d_out, int out_size)
{
    const float* x  = (const float*)d_in[0];
    const float* wq = (const float*)d_in[1];
    const float* bq = (const float*)d_in[2];
    const float* wk = (const float*)d_in[3];
    const float* bk = (const float*)d_in[4];
    const float* wv = (const float*)d_in[5];
    const float* bv = (const float*)d_in[6];
    const float* wo = (const float*)d_in[7];
    const float* bo = (const float*)d_in[8];
    float* out = (float*)d_out;

    dim3 blk(16, 16);

    // QKV 1x1 convs
    conv1x1_kernel<<<dim3(HWs / 128, BT), blk>>>(x, wq, bq, 0);
    conv1x1_kernel<<<dim3(HWs / 128, BT), blk>>>(x, wk, bk, 1);
    conv1x1_kernel<<<dim3(HWs / 128, BT), blk>>>(x, wv, bv, 2);

    // per-scale windowed attention
    // scale 0: ph=128, oh=1, n=8,  d=524288
    {
        const int n = 8, d = 524288, cs = 0, lph = 7, loh = 0, S = 1024;
        float isd = (float)(1.0 / sqrt((double)d));
        scores_kernel<8, 8, 1, 1><<<dim3(1, NB, S), blk>>>(n, cs, lph, loh, 1, d / S);
        softmax_kernel<<<dim3(n, NB), 256>>>(n, S, isd);
        av_kernel<8, 1><<<dim3(d / 64, 1, NB), blk>>>(n, cs, lph, loh);
    }
    // scale 1: ph=64, oh=2, n=32, d=131072
    {
        const int n = 32, d = 131072, cs = 32, lph = 6, loh = 1, S = 512;
        float isd = (float)(1.0 / sqrt((double)d));
        scores_kernel<32, 32, 2, 2><<<dim3(1, NB, S), blk>>>(n, cs, lph, loh, 1, d / S);
        softmax_kernel<<<dim3(n, NB), 256>>>(n, S, isd);
        av_kernel<32, 2><<<dim3(d / 64, 1, NB), blk>>>(n, cs, lph, loh);
    }
    // scale 2: ph=32, oh=4, n=128, d=32768
    {
        const int n = 128, d = 32768, cs = 64, lph = 5, loh = 2, S = 32;
        float isd = (float)(1.0 / sqrt((double)d));
        scores_kernel<32, 32, 2, 2><<<dim3(16, NB, S), blk>>>(n, cs, lph, loh, 4, d / S);
        softmax_kernel<<<dim3(n, NB), 256>>>(n, S, isd);
        av_kernel<32, 2><<<dim3(d / 64, 4, NB), blk>>>(n, cs, lph, loh);
    }
    // scale 3: ph=16, oh=8, n=512, d=8192
    {
        const int n = 512, d = 8192, cs = 96, lph = 4, loh = 3, S = 8;
        float isd = (float)(1.0 / sqrt((double)d));
        scores_kernel<64, 64, 4, 4><<<dim3(64, NB, S), blk>>>(n, cs, lph, loh, 8, d / S);
        softmax_kernel<<<dim3(n, NB), 256>>>(n, S, isd);
        av_kernel<64, 4><<<dim3(d / 64, 8, NB), blk>>>(n, cs, lph, loh);
    }

    // output 3x3 conv + bias + relu
    conv3x3_kernel<<<dim3(Hd, BT), blk>>>(wo, bo, out);

    (void)in_sizes; (void)n_in; (void)out_size;
}